// round 5
// baseline (speedup 1.0000x reference)
#include <cuda_runtime.h>
#include <math.h>

#define NN    10000
#define HH    4
#define FF    128
#define HF    (HH*FF)      // 512
#define EE    320000
#define ET    (EE+NN)      // 330000 edges incl self-loops
#define SLOPE 0.2f

// ---------------- scratch (device globals; no allocation allowed) ----------
__device__ float g_hp  [(size_t)NN*HF];   // projected features [N,H,F]
__device__ float g_acc [(size_t)NN*HF];   // aggregation accumulator [N,H,F]
__device__ float g_x   [(size_t)NN*FF];   // inter-layer features [N,F]
__device__ float g_z   [(size_t)NN*FF];   // encoder output z [N,F]
__device__ float g_als [NN*HH];
__device__ float g_ald [NN*HH];
__device__ float g_m   [NN*HH];
__device__ float g_s   [NN*HH];
__device__ float g_eval[(size_t)ET*HH];
__device__ int   g_is64;                  // edge_index dtype flag

// --------- edge-index dtype sniffer ----------------------------------------
__global__ void detect_ei_kernel(const int* __restrict__ ei32)
{
    __shared__ int any;
    if (threadIdx.x == 0) any = 0;
    __syncthreads();
    for (int i = threadIdx.x; i < 4096; i += blockDim.x)
        if (ei32[2 * i + 1] != 0) atomicOr(&any, 1);
    __syncthreads();
    if (threadIdx.x == 0) g_is64 = (any == 0);
}

__device__ __forceinline__ void edge_sd(const int* __restrict__ ei32, int e,
                                        int& s, int& d)
{
    if (e >= EE) { s = d = e - EE; return; }          // self-loop
    if (g_is64) { s = ei32[2 * e]; d = ei32[2 * (EE + e)]; }
    else        { s = ei32[e];     d = ei32[EE + e]; }
}

__device__ __forceinline__ bool valid_nd(int s, int d)
{
    return ((unsigned)s < NN) && ((unsigned)d < NN);
}

// ---------------- SGEMM v2: 128x128x16, double-buffered, 8x8 microtile ------
// C[M,N] = A[M,K] @ op(B), row-major.
// TRANSB=false: B is [K,N];  TRANSB=true: B is [N,K] (C = A @ B^T).
// ACT: 0=none, 1=sigmoid.  Requires K % 16 == 0.
template<int ACT, bool TRANSB>
__global__ __launch_bounds__(256, 2)
void sgemm_v2(int M, int N, int K,
              const float* __restrict__ A,
              const float* __restrict__ B,
              float* __restrict__ C)
{
    __shared__ float As[2][16][132];
    __shared__ float Bs[2][16][132];

    const int tid = threadIdx.x;
    const int tx  = tid & 15;              // N dir (0..15)
    const int ty  = tid >> 4;              // M dir (0..15)
    const int rowBase = blockIdx.y * 128;
    const int colBase = blockIdx.x * 128;

    // A load mapping: 128 rows x 16 cols, float4 along K
    const int aRow = tid >> 2;             // 0..63 (and +64)
    const int aCol = (tid & 3) * 4;        // 0,4,8,12
    // B load mapping (K,N): 16 rows x 128 cols, float4 along N
    const int bRow = tid >> 5;             // 0..7 (and +8)
    const int bCol = (tid & 31) * 4;       // 0..124
    // B load mapping (N,K): 128 rows x 16 cols, float4 along K
    const int nRow = tid >> 2;             // 0..63 (and +64)
    const int nCol = (tid & 3) * 4;

    float acc[8][8];
    #pragma unroll
    for (int i = 0; i < 8; i++)
        #pragma unroll
        for (int j = 0; j < 8; j++) acc[i][j] = 0.f;

    const int T = K >> 4;

    // ---- helpers to fetch one tile's worth of global data into registers ---
    auto fetchA = [&](int k0, float4& a0, float4& a1) {
        const int r0 = rowBase + aRow, r1 = r0 + 64;
        a0 = (r0 < M) ? *reinterpret_cast<const float4*>(&A[(size_t)r0 * K + k0 + aCol])
                      : make_float4(0.f, 0.f, 0.f, 0.f);
        a1 = (r1 < M) ? *reinterpret_cast<const float4*>(&A[(size_t)r1 * K + k0 + aCol])
                      : make_float4(0.f, 0.f, 0.f, 0.f);
    };
    auto fetchB = [&](int k0, float4& b0, float4& b1) {
        if (!TRANSB) {
            const int c = colBase + bCol;
            b0 = (c < N) ? *reinterpret_cast<const float4*>(&B[(size_t)(k0 + bRow) * N + c])
                         : make_float4(0.f, 0.f, 0.f, 0.f);
            b1 = (c < N) ? *reinterpret_cast<const float4*>(&B[(size_t)(k0 + bRow + 8) * N + c])
                         : make_float4(0.f, 0.f, 0.f, 0.f);
        } else {
            const int n0 = colBase + nRow, n1 = n0 + 64;
            b0 = (n0 < N) ? *reinterpret_cast<const float4*>(&B[(size_t)n0 * K + k0 + nCol])
                          : make_float4(0.f, 0.f, 0.f, 0.f);
            b1 = (n1 < N) ? *reinterpret_cast<const float4*>(&B[(size_t)n1 * K + k0 + nCol])
                          : make_float4(0.f, 0.f, 0.f, 0.f);
        }
    };
    auto storeA = [&](int buf, const float4& a0, const float4& a1) {
        As[buf][aCol + 0][aRow] = a0.x;  As[buf][aCol + 1][aRow] = a0.y;
        As[buf][aCol + 2][aRow] = a0.z;  As[buf][aCol + 3][aRow] = a0.w;
        As[buf][aCol + 0][aRow + 64] = a1.x;  As[buf][aCol + 1][aRow + 64] = a1.y;
        As[buf][aCol + 2][aRow + 64] = a1.z;  As[buf][aCol + 3][aRow + 64] = a1.w;
    };
    auto storeB = [&](int buf, const float4& b0, const float4& b1) {
        if (!TRANSB) {
            *reinterpret_cast<float4*>(&Bs[buf][bRow][bCol])     = b0;
            *reinterpret_cast<float4*>(&Bs[buf][bRow + 8][bCol]) = b1;
        } else {
            Bs[buf][nCol + 0][nRow] = b0.x;  Bs[buf][nCol + 1][nRow] = b0.y;
            Bs[buf][nCol + 2][nRow] = b0.z;  Bs[buf][nCol + 3][nRow] = b0.w;
            Bs[buf][nCol + 0][nRow + 64] = b1.x;  Bs[buf][nCol + 1][nRow + 64] = b1.y;
            Bs[buf][nCol + 2][nRow + 64] = b1.z;  Bs[buf][nCol + 3][nRow + 64] = b1.w;
        }
    };

    // prologue: tile 0 -> buf 0
    {
        float4 a0, a1, b0, b1;
        fetchA(0, a0, a1);
        fetchB(0, b0, b1);
        storeA(0, a0, a1);
        storeB(0, b0, b1);
    }
    __syncthreads();

    int buf = 0;
    for (int t = 0; t < T; t++) {
        float4 a0, a1, b0, b1;
        const bool more = (t + 1 < T);
        if (more) {
            fetchA((t + 1) << 4, a0, a1);
            fetchB((t + 1) << 4, b0, b1);
        }

        #pragma unroll
        for (int kk = 0; kk < 16; kk++) {
            float ra[8], rb[8];
            #pragma unroll
            for (int i = 0; i < 8; i++) ra[i] = As[buf][kk][ty * 8 + i];
            #pragma unroll
            for (int j = 0; j < 8; j++) rb[j] = Bs[buf][kk][tx * 8 + j];
            #pragma unroll
            for (int i = 0; i < 8; i++)
                #pragma unroll
                for (int j = 0; j < 8; j++)
                    acc[i][j] = fmaf(ra[i], rb[j], acc[i][j]);
        }

        if (more) {
            storeA(buf ^ 1, a0, a1);
            storeB(buf ^ 1, b0, b1);
        }
        __syncthreads();
        buf ^= 1;
    }

    #pragma unroll
    for (int i = 0; i < 8; i++) {
        const int row = rowBase + ty * 8 + i;
        if (row >= M) continue;
        #pragma unroll
        for (int j = 0; j < 8; j++) {
            const int col = colBase + tx * 8 + j;
            if (col >= N) continue;
            float v = acc[i][j];
            if (ACT == 1) v = 1.f / (1.f + __expf(-v));
            C[(size_t)row * N + col] = v;
        }
    }
}

// --------- per-node attention logits: als/ald[n,h] = <h[n,h,:], a[h,:]> -----
__global__ void attn_logits_kernel(const float* __restrict__ hp,
                                   const float* __restrict__ a_src,
                                   const float* __restrict__ a_dst)
{
    const int warp = (blockIdx.x * blockDim.x + threadIdx.x) >> 5;
    const int lane = threadIdx.x & 31;
    if (warp >= NN * HH) return;
    const int n = warp / HH, h = warp % HH;
    const float* hv = hp + (size_t)n * HF + h * FF;
    float s1 = 0.f, s2 = 0.f;
    #pragma unroll
    for (int j = 0; j < 4; j++) {
        const int f = lane + 32 * j;
        const float v = hv[f];
        s1 = fmaf(v, a_src[h * FF + f], s1);
        s2 = fmaf(v, a_dst[h * FF + f], s2);
    }
    #pragma unroll
    for (int o = 16; o; o >>= 1) {
        s1 += __shfl_xor_sync(0xffffffffu, s1, o);
        s2 += __shfl_xor_sync(0xffffffffu, s2, o);
    }
    if (lane == 0) { g_als[warp] = s1; g_ald[warp] = s2; }
}

// --------- init m=-inf, s=0, acc=0 -----------------------------------------
__global__ void init_kernel()
{
    const size_t total = (size_t)NN * HF;
    for (size_t i = blockIdx.x * blockDim.x + threadIdx.x; i < total;
         i += (size_t)gridDim.x * blockDim.x) {
        g_acc[i] = 0.f;
        if (i < NN * HH) { g_m[i] = -INFINITY; g_s[i] = 0.f; }
    }
}

__device__ __forceinline__ void atomicMaxFloat(float* addr, float val)
{
    if (val >= 0.f) atomicMax((int*)addr, __float_as_int(val));
    else            atomicMin((unsigned int*)addr, __float_as_uint(val));
}

// --------- edge pass 1: leaky-relu logits + segment max (thread/edge) -------
__global__ void edge_logits_kernel(const int* __restrict__ ei)
{
    const int e = blockIdx.x * blockDim.x + threadIdx.x;
    if (e >= ET) return;
    int s, d; edge_sd(ei, e, s, d);
    if (!valid_nd(s, d)) {
        g_eval[(size_t)e * 4 + 0] = -INFINITY; g_eval[(size_t)e * 4 + 1] = -INFINITY;
        g_eval[(size_t)e * 4 + 2] = -INFINITY; g_eval[(size_t)e * 4 + 3] = -INFINITY;
        return;
    }
    const float4 as4 = *reinterpret_cast<const float4*>(&g_als[s * 4]);
    const float4 ad4 = *reinterpret_cast<const float4*>(&g_ald[d * 4]);
    float v[4] = { as4.x + ad4.x, as4.y + ad4.y, as4.z + ad4.z, as4.w + ad4.w };
    #pragma unroll
    for (int h = 0; h < 4; h++) {
        v[h] = v[h] > 0.f ? v[h] : SLOPE * v[h];
        atomicMaxFloat(&g_m[d * 4 + h], v[h]);
    }
    *reinterpret_cast<float4*>(&g_eval[(size_t)e * 4]) =
        make_float4(v[0], v[1], v[2], v[3]);
}

// --------- edge pass 2: exp + segment sum (thread/edge) ---------------------
__global__ void edge_exp_kernel(const int* __restrict__ ei)
{
    const int e = blockIdx.x * blockDim.x + threadIdx.x;
    if (e >= ET) return;
    int s, d; edge_sd(ei, e, s, d);
    if (!valid_nd(s, d)) {
        *reinterpret_cast<float4*>(&g_eval[(size_t)e * 4]) =
            make_float4(0.f, 0.f, 0.f, 0.f);
        return;
    }
    const float4 m4 = *reinterpret_cast<const float4*>(&g_m[d * 4]);
    float4 ev = *reinterpret_cast<const float4*>(&g_eval[(size_t)e * 4]);
    ev.x = __expf(ev.x - m4.x);
    ev.y = __expf(ev.y - m4.y);
    ev.z = __expf(ev.z - m4.z);
    ev.w = __expf(ev.w - m4.w);
    *reinterpret_cast<float4*>(&g_eval[(size_t)e * 4]) = ev;
    atomicAdd(&g_s[d * 4 + 0], ev.x);
    atomicAdd(&g_s[d * 4 + 1], ev.y);
    atomicAdd(&g_s[d * 4 + 2], ev.z);
    atomicAdd(&g_s[d * 4 + 3], ev.w);
}

// --------- edge pass 3: scatter messages (warp per edge, all heads) ---------
__global__ void edge_msg_kernel(const int* __restrict__ ei)
{
    const int warp = (blockIdx.x * blockDim.x + threadIdx.x) >> 5;
    const int lane = threadIdx.x & 31;
    if (warp >= ET) return;
    const int e = warp;
    int s, d; edge_sd(ei, e, s, d);
    if (!valid_nd(s, d)) return;
    const int h = lane >> 3;                      // 8 lanes per head
    const float alpha = g_eval[(size_t)e * 4 + h] / g_s[d * 4 + h];
    const float* hs = &g_hp[(size_t)s * HF + lane * 16];
    float*       ad = &g_acc[(size_t)d * HF + lane * 16];
    #pragma unroll
    for (int q = 0; q < 4; q++) {
        const float4 hv = *reinterpret_cast<const float4*>(hs + q * 4);
        atomicAdd(ad + q * 4 + 0, hv.x * alpha);
        atomicAdd(ad + q * 4 + 1, hv.y * alpha);
        atomicAdd(ad + q * 4 + 2, hv.z * alpha);
        atomicAdd(ad + q * 4 + 3, hv.w * alpha);
    }
}

// --------- finalize: head mean + bias + activation --------------------------
__global__ void finalize_kernel(const float* __restrict__ b, float* __restrict__ out,
                                int act, float* __restrict__ mirror)
{
    const int idx = blockIdx.x * blockDim.x + threadIdx.x;
    if (idx >= NN * FF) return;
    const int n = idx / FF, f = idx % FF;
    const float* a = &g_acc[(size_t)n * HF];
    float v = (a[f] + a[FF + f] + a[2 * FF + f] + a[3 * FF + f]) * 0.25f + b[f];
    v = act == 0 ? fmaxf(v, 0.f) : tanhf(v);
    out[(size_t)n * FF + f] = v;
    if (mirror) mirror[(size_t)n * FF + f] = v;
}

// ---------------------------------------------------------------------------
static void run_layer(const float* x, int Din, const float* W,
                      const float* a_s, const float* a_d, const float* b,
                      const int* ei, float* hp, float* out, int act,
                      float* mirror)
{
    {
        dim3 grid((HF + 127) / 128, (NN + 127) / 128);
        sgemm_v2<0, false><<<grid, 256>>>(NN, HF, Din, x, W, hp);
    }
    attn_logits_kernel<<<(NN * HH * 32 + 255) / 256, 256>>>(hp, a_s, a_d);
    init_kernel<<<1024, 256>>>();
    edge_logits_kernel<<<(ET + 255) / 256, 256>>>(ei);
    edge_exp_kernel   <<<(ET + 255) / 256, 256>>>(ei);
    edge_msg_kernel   <<<(ET * 32 + 255) / 256, 256>>>(ei);
    finalize_kernel<<<(NN * FF + 255) / 256, 256>>>(b, out, act, mirror);
}

extern "C" void kernel_launch(void* const* d_in, const int* in_sizes, int n_in,
                              void* d_out, int out_size)
{
    // ---- size-based input classification (robust to metadata ordering) ----
    const int SZ_X  = NN * NN;      // 100,000,000
    const int SZ_EI = 2 * EE;       // 640,000
    const int SZ_W0 = NN * HF;      // 5,120,000
    const int SZ_W  = FF * HF;      // 65,536
    const int SZ_A  = HH * FF;      // 512
    const int SZ_B  = FF;           // 128

    const float* x  = nullptr;
    const int*   ei = nullptr;
    const float* W [4] = {nullptr, nullptr, nullptr, nullptr};
    const float* AS[4] = {nullptr, nullptr, nullptr, nullptr};
    const float* AD[4] = {nullptr, nullptr, nullptr, nullptr};
    const float* B [4] = {nullptr, nullptr, nullptr, nullptr};

    int wIdx = 1, bIdx = 0;
    int aPos[8]; const float* aPtr[8]; int nA = 0;

    for (int i = 0; i < n_in; i++) {
        const int s = in_sizes[i];
        if      (s == SZ_X)  x = (const float*)d_in[i];
        else if (s == SZ_EI) ei = (const int*)d_in[i];
        else if (s == SZ_W0) W[0] = (const float*)d_in[i];
        else if (s == SZ_W)  { if (wIdx < 4) W[wIdx++] = (const float*)d_in[i]; }
        else if (s == SZ_A)  { if (nA < 8) { aPos[nA] = i; aPtr[nA] = (const float*)d_in[i]; nA++; } }
        else if (s == SZ_B)  { if (bIdx < 4) B[bIdx++] = (const float*)d_in[i]; }
    }

    bool contiguous8 = (nA == 8);
    for (int i = 1; i < nA; i++)
        if (aPos[i] != aPos[0] + i) { contiguous8 = false; break; }

    if (contiguous8) {
        for (int i = 0; i < 4; i++) { AS[i] = aPtr[i]; AD[i] = aPtr[4 + i]; }
    } else {
        for (int i = 0; i < 4; i++) { AS[i] = aPtr[2 * i]; AD[i] = aPtr[2 * i + 1]; }
    }

    float* hp;  cudaGetSymbolAddress((void**)&hp,  g_hp);
    float* xbuf;cudaGetSymbolAddress((void**)&xbuf,g_x);
    float* zbuf;cudaGetSymbolAddress((void**)&zbuf,g_z);

    float* out = (float*)d_out;                     // adj_recon [N,N]
    const long long need = (long long)NN * NN + (long long)NN * FF;
    float* zmirror = ((long long)out_size >= need) ? out + (size_t)NN * NN : nullptr;

    detect_ei_kernel<<<1, 256>>>(ei);

    run_layer(x,    NN, W[0], AS[0], AD[0], B[0], ei, hp, xbuf, 0, nullptr);
    run_layer(xbuf, FF, W[1], AS[1], AD[1], B[1], ei, hp, xbuf, 0, nullptr);
    run_layer(xbuf, FF, W[2], AS[2], AD[2], B[2], ei, hp, xbuf, 0, nullptr);
    run_layer(xbuf, FF, W[3], AS[3], AD[3], B[3], ei, hp, zbuf, 1, zmirror);

    // decode: adj = sigmoid(z @ z^T)  (NT variant, no explicit transpose)
    {
        dim3 grid((NN + 127) / 128, (NN + 127) / 128);
        sgemm_v2<1, true><<<grid, 256>>>(NN, NN, FF, zbuf, zbuf, out);
    }
}

// round 6
// speedup vs baseline: 1.4093x; 1.4093x over previous
#include <cuda_runtime.h>
#include <math.h>

#define NN    10000
#define HH    4
#define FF    128
#define HF    (HH*FF)      // 512
#define EE    320000
#define ET    (EE+NN)      // 330000 edges incl self-loops
#define SLOPE 0.2f

// ---------------- scratch (device globals; no allocation allowed) ----------
__device__ float g_hp  [(size_t)NN*HF];   // projected features [N,H,F]
__device__ float g_x   [(size_t)NN*FF];   // inter-layer features [N,F]
__device__ float g_z   [(size_t)NN*FF];   // encoder output z [N,F]
__device__ float g_zt  [(size_t)FF*NN];   // z transposed [F,N]
__device__ float g_als [NN*HH];
__device__ float g_ald [NN*HH];
__device__ float g_eval[(size_t)ET*HH];   // per-edge exp values (CSR order)
__device__ int   g_is64;                  // edge_index dtype flag
// CSR by destination node
__device__ int   g_deg [NN];
__device__ int   g_off [NN+1];
__device__ int   g_cur [NN];
__device__ int   g_eid [ET];

// --------- edge-index dtype sniffer ----------------------------------------
__global__ void detect_ei_kernel(const int* __restrict__ ei32)
{
    __shared__ int any;
    if (threadIdx.x == 0) any = 0;
    __syncthreads();
    for (int i = threadIdx.x; i < 4096; i += blockDim.x)
        if (ei32[2 * i + 1] != 0) atomicOr(&any, 1);
    __syncthreads();
    if (threadIdx.x == 0) g_is64 = (any == 0);
}

__device__ __forceinline__ void edge_sd(const int* __restrict__ ei32, int e,
                                        int& s, int& d)
{
    if (e >= EE) { s = d = e - EE; return; }          // self-loop
    if (g_is64) { s = ei32[2 * e]; d = ei32[2 * (EE + e)]; }
    else        { s = ei32[e];     d = ei32[EE + e]; }
}

__device__ __forceinline__ bool valid_nd(int s, int d)
{
    return ((unsigned)s < NN) && ((unsigned)d < NN);
}

// ---------------- CSR construction ------------------------------------------
__global__ void csr_zero_kernel()
{
    const int n = blockIdx.x * blockDim.x + threadIdx.x;
    if (n < NN) g_deg[n] = 0;
}

__global__ void csr_hist_kernel(const int* __restrict__ ei)
{
    const int e = blockIdx.x * blockDim.x + threadIdx.x;
    if (e >= ET) return;
    int s, d; edge_sd(ei, e, s, d);
    if (valid_nd(s, d)) atomicAdd(&g_deg[d], 1);
}

// single-block exclusive scan of g_deg -> g_off (and g_cur)
__global__ void csr_scan_kernel()
{
    __shared__ int warp_sums[32];
    const int tid  = threadIdx.x;          // 1024 threads
    const int lane = tid & 31, wid = tid >> 5;
    const int base = tid * 10;

    int local[10];
    int sum = 0;
    #pragma unroll
    for (int k = 0; k < 10; k++) {
        const int n = base + k;
        const int v = (n < NN) ? g_deg[n] : 0;
        local[k] = sum;
        sum += v;
    }
    int x = sum;
    #pragma unroll
    for (int o = 1; o < 32; o <<= 1) {
        const int y = __shfl_up_sync(0xffffffffu, x, o);
        if (lane >= o) x += y;
    }
    if (lane == 31) warp_sums[wid] = x;
    __syncthreads();
    if (wid == 0) {
        int w = warp_sums[lane];
        #pragma unroll
        for (int o = 1; o < 32; o <<= 1) {
            const int y = __shfl_up_sync(0xffffffffu, w, o);
            if (lane >= o) w += y;
        }
        warp_sums[lane] = w;
    }
    __syncthreads();
    const int thread_excl = x - sum + (wid > 0 ? warp_sums[wid - 1] : 0);
    #pragma unroll
    for (int k = 0; k < 10; k++) {
        const int n = base + k;
        if (n < NN) {
            const int o = thread_excl + local[k];
            g_off[n] = o;
            g_cur[n] = o;
        }
    }
    if (tid == 1023) g_off[NN] = thread_excl + sum;
}

__global__ void csr_scatter_kernel(const int* __restrict__ ei)
{
    const int e = blockIdx.x * blockDim.x + threadIdx.x;
    if (e >= ET) return;
    int s, d; edge_sd(ei, e, s, d);
    if (!valid_nd(s, d)) return;
    const int pos = atomicAdd(&g_cur[d], 1);
    g_eid[pos] = e;
}

// ---------------- SGEMM 128x128x8, 256 thr, 8x8 microtile (R4 baseline) -----
template<int ACT>
__global__ void sgemm128(int M, int N, int K,
                         const float* __restrict__ A,
                         const float* __restrict__ B,
                         float* __restrict__ C)
{
    __shared__ float As[8][128];
    __shared__ float Bs[8][128];

    const int tid = threadIdx.x;
    const int tx  = tid & 15;
    const int ty  = tid >> 4;
    const int rowBase = blockIdx.y * 128;
    const int colBase = blockIdx.x * 128;

    const int aRow = tid >> 1;
    const int aCol = (tid & 1) * 4;
    const int bRow = tid >> 5;
    const int bCol = (tid & 31) * 4;

    float acc[8][8];
    #pragma unroll
    for (int i = 0; i < 8; i++)
        #pragma unroll
        for (int j = 0; j < 8; j++) acc[i][j] = 0.f;

    const int ar = rowBase + aRow;
    const int bc = colBase + bCol;

    for (int k0 = 0; k0 < K; k0 += 8) {
        float4 av = make_float4(0.f, 0.f, 0.f, 0.f);
        if (ar < M)
            av = *reinterpret_cast<const float4*>(&A[(size_t)ar * K + k0 + aCol]);
        As[aCol + 0][aRow] = av.x;
        As[aCol + 1][aRow] = av.y;
        As[aCol + 2][aRow] = av.z;
        As[aCol + 3][aRow] = av.w;

        float4 bv = make_float4(0.f, 0.f, 0.f, 0.f);
        if (bc < N)
            bv = *reinterpret_cast<const float4*>(&B[(size_t)(k0 + bRow) * N + bc]);
        *reinterpret_cast<float4*>(&Bs[bRow][bCol]) = bv;

        __syncthreads();

        #pragma unroll
        for (int k = 0; k < 8; k++) {
            float ra[8], rb[8];
            #pragma unroll
            for (int i = 0; i < 8; i++) ra[i] = As[k][ty * 8 + i];
            #pragma unroll
            for (int j = 0; j < 8; j++) rb[j] = Bs[k][tx * 8 + j];
            #pragma unroll
            for (int i = 0; i < 8; i++)
                #pragma unroll
                for (int j = 0; j < 8; j++)
                    acc[i][j] = fmaf(ra[i], rb[j], acc[i][j]);
        }
        __syncthreads();
    }

    #pragma unroll
    for (int i = 0; i < 8; i++) {
        const int row = rowBase + ty * 8 + i;
        if (row >= M) continue;
        #pragma unroll
        for (int j = 0; j < 8; j++) {
            const int col = colBase + tx * 8 + j;
            if (col >= N) continue;
            float v = acc[i][j];
            if (ACT == 1) v = 1.f / (1.f + __expf(-v));
            C[(size_t)row * N + col] = v;
        }
    }
}

// --------- per-node attention logits: als/ald[n,h] = <h[n,h,:], a[h,:]> -----
__global__ void attn_logits_kernel(const float* __restrict__ hp,
                                   const float* __restrict__ a_src,
                                   const float* __restrict__ a_dst)
{
    const int warp = (blockIdx.x * blockDim.x + threadIdx.x) >> 5;
    const int lane = threadIdx.x & 31;
    if (warp >= NN * HH) return;
    const int n = warp / HH, h = warp % HH;
    const float* hv = hp + (size_t)n * HF + h * FF;
    float s1 = 0.f, s2 = 0.f;
    #pragma unroll
    for (int j = 0; j < 4; j++) {
        const int f = lane + 32 * j;
        const float v = hv[f];
        s1 = fmaf(v, a_src[h * FF + f], s1);
        s2 = fmaf(v, a_dst[h * FF + f], s2);
    }
    #pragma unroll
    for (int o = 16; o; o >>= 1) {
        s1 += __shfl_xor_sync(0xffffffffu, s1, o);
        s2 += __shfl_xor_sync(0xffffffffu, s2, o);
    }
    if (lane == 0) { g_als[warp] = s1; g_ald[warp] = s2; }
}

// ---------------- fused per-dst-node softmax + aggregate --------------------
// One block (128 threads) per destination node. Replaces init/edge1/edge2/
// edge3/finalize: no global atomics, no segment buffers.
// act: 0 = relu, 1 = tanh.
__global__ __launch_bounds__(128)
void fused_agg_kernel(const int* __restrict__ ei,
                      const float* __restrict__ b,
                      float* __restrict__ out, int act,
                      float* __restrict__ mirror)
{
    const int n   = blockIdx.x;
    const int tid = threadIdx.x;
    const int lane = tid & 31, wid = tid >> 5;
    const int off = g_off[n];
    const int deg = g_off[n + 1] - off;

    __shared__ float warp_red[4][4];       // [warp][head]
    __shared__ float smax[4], sinv[4];
    __shared__ float alpha_sm[128][4];
    __shared__ int   ssrc_sm[128];
    __shared__ float feat[HF];

    const float4 ald4 = *reinterpret_cast<const float4*>(&g_ald[n * 4]);

    // ---- Phase A: logits + block max per head -----------------------------
    float mx[4] = { -INFINITY, -INFINITY, -INFINITY, -INFINITY };
    for (int i = tid; i < deg; i += 128) {
        const int e = g_eid[off + i];
        int s, d; edge_sd(ei, e, s, d);
        const float4 as4 = *reinterpret_cast<const float4*>(&g_als[s * 4]);
        float v[4] = { as4.x + ald4.x, as4.y + ald4.y,
                       as4.z + ald4.z, as4.w + ald4.w };
        #pragma unroll
        for (int h = 0; h < 4; h++) {
            v[h] = v[h] > 0.f ? v[h] : SLOPE * v[h];
            mx[h] = fmaxf(mx[h], v[h]);
        }
        *reinterpret_cast<float4*>(&g_eval[(size_t)(off + i) * 4]) =
            make_float4(v[0], v[1], v[2], v[3]);
    }
    #pragma unroll
    for (int h = 0; h < 4; h++)
        #pragma unroll
        for (int o = 16; o; o >>= 1)
            mx[h] = fmaxf(mx[h], __shfl_xor_sync(0xffffffffu, mx[h], o));
    if (lane == 0)
        #pragma unroll
        for (int h = 0; h < 4; h++) warp_red[wid][h] = mx[h];
    __syncthreads();
    if (tid == 0) {
        #pragma unroll
        for (int h = 0; h < 4; h++)
            smax[h] = fmaxf(fmaxf(warp_red[0][h], warp_red[1][h]),
                            fmaxf(warp_red[2][h], warp_red[3][h]));
    }
    __syncthreads();

    // ---- Phase B: exp + block sum per head --------------------------------
    float sm[4] = { 0.f, 0.f, 0.f, 0.f };
    const float m0 = smax[0], m1 = smax[1], m2 = smax[2], m3 = smax[3];
    for (int i = tid; i < deg; i += 128) {
        float4 v = *reinterpret_cast<const float4*>(&g_eval[(size_t)(off + i) * 4]);
        v.x = __expf(v.x - m0); v.y = __expf(v.y - m1);
        v.z = __expf(v.z - m2); v.w = __expf(v.w - m3);
        *reinterpret_cast<float4*>(&g_eval[(size_t)(off + i) * 4]) = v;
        sm[0] += v.x; sm[1] += v.y; sm[2] += v.z; sm[3] += v.w;
    }
    #pragma unroll
    for (int h = 0; h < 4; h++)
        #pragma unroll
        for (int o = 16; o; o >>= 1)
            sm[h] += __shfl_xor_sync(0xffffffffu, sm[h], o);
    if (lane == 0)
        #pragma unroll
        for (int h = 0; h < 4; h++) warp_red[wid][h] = sm[h];
    __syncthreads();
    if (tid == 0) {
        #pragma unroll
        for (int h = 0; h < 4; h++) {
            const float t = warp_red[0][h] + warp_red[1][h] +
                            warp_red[2][h] + warp_red[3][h];
            sinv[h] = (t > 0.f) ? 1.f / t : 0.f;
        }
    }
    __syncthreads();

    // ---- Phase C: weighted gather of h[src] -------------------------------
    const int myh = tid >> 5;                       // head of my 4 features
    const float i0 = sinv[0], i1 = sinv[1], i2 = sinv[2], i3 = sinv[3];
    float4 acc = make_float4(0.f, 0.f, 0.f, 0.f);
    for (int base = 0; base < deg; base += 128) {
        const int cnt = min(128, deg - base);
        __syncthreads();
        if (tid < cnt) {
            const int e = g_eid[off + base + tid];
            int s, d; edge_sd(ei, e, s, d);
            ssrc_sm[tid] = s;
            const float4 v =
                *reinterpret_cast<const float4*>(&g_eval[(size_t)(off + base + tid) * 4]);
            alpha_sm[tid][0] = v.x * i0;
            alpha_sm[tid][1] = v.y * i1;
            alpha_sm[tid][2] = v.z * i2;
            alpha_sm[tid][3] = v.w * i3;
        }
        __syncthreads();
        for (int j = 0; j < cnt; j++) {
            const int s = ssrc_sm[j];
            const float a = alpha_sm[j][myh];
            const float4 hv = *reinterpret_cast<const float4*>(
                &g_hp[(size_t)s * HF + tid * 4]);
            acc.x = fmaf(a, hv.x, acc.x);
            acc.y = fmaf(a, hv.y, acc.y);
            acc.z = fmaf(a, hv.z, acc.z);
            acc.w = fmaf(a, hv.w, acc.w);
        }
    }
    *reinterpret_cast<float4*>(&feat[tid * 4]) = acc;
    __syncthreads();

    // ---- epilogue: head mean + bias + activation --------------------------
    {
        const int f = tid;                          // 128 threads = 128 features
        float v = (feat[f] + feat[FF + f] + feat[2 * FF + f] + feat[3 * FF + f])
                  * 0.25f + b[f];
        v = (act == 0) ? fmaxf(v, 0.f) : tanhf(v);
        out[(size_t)n * FF + f] = v;
        if (mirror) mirror[(size_t)n * FF + f] = v;
    }
}

__global__ void transpose_z_kernel(const float* __restrict__ z, float* __restrict__ zt)
{
    const int idx = blockIdx.x * blockDim.x + threadIdx.x;
    if (idx >= NN * FF) return;
    const int n = idx / FF, f = idx % FF;
    zt[(size_t)f * NN + n] = z[idx];
}

// ---------------------------------------------------------------------------
static void run_layer(const float* x, int Din, const float* W,
                      const float* a_s, const float* a_d, const float* b,
                      const int* ei, float* hp, float* out, int act,
                      float* mirror)
{
    {
        dim3 grid((HF + 127) / 128, (NN + 127) / 128);
        sgemm128<0><<<grid, 256>>>(NN, HF, Din, x, W, hp);
    }
    attn_logits_kernel<<<(NN * HH * 32 + 255) / 256, 256>>>(hp, a_s, a_d);
    fused_agg_kernel<<<NN, 128>>>(ei, b, out, act, mirror);
}

extern "C" void kernel_launch(void* const* d_in, const int* in_sizes, int n_in,
                              void* d_out, int out_size)
{
    // ---- size-based input classification ----------------------------------
    const int SZ_X  = NN * NN;
    const int SZ_EI = 2 * EE;
    const int SZ_W0 = NN * HF;
    const int SZ_W  = FF * HF;
    const int SZ_A  = HH * FF;
    const int SZ_B  = FF;

    const float* x  = nullptr;
    const int*   ei = nullptr;
    const float* W [4] = {nullptr, nullptr, nullptr, nullptr};
    const float* AS[4] = {nullptr, nullptr, nullptr, nullptr};
    const float* AD[4] = {nullptr, nullptr, nullptr, nullptr};
    const float* B [4] = {nullptr, nullptr, nullptr, nullptr};

    int wIdx = 1, bIdx = 0;
    int aPos[8]; const float* aPtr[8]; int nA = 0;

    for (int i = 0; i < n_in; i++) {
        const int s = in_sizes[i];
        if      (s == SZ_X)  x = (const float*)d_in[i];
        else if (s == SZ_EI) ei = (const int*)d_in[i];
        else if (s == SZ_W0) W[0] = (const float*)d_in[i];
        else if (s == SZ_W)  { if (wIdx < 4) W[wIdx++] = (const float*)d_in[i]; }
        else if (s == SZ_A)  { if (nA < 8) { aPos[nA] = i; aPtr[nA] = (const float*)d_in[i]; nA++; } }
        else if (s == SZ_B)  { if (bIdx < 4) B[bIdx++] = (const float*)d_in[i]; }
    }

    bool contiguous8 = (nA == 8);
    for (int i = 1; i < nA; i++)
        if (aPos[i] != aPos[0] + i) { contiguous8 = false; break; }

    if (contiguous8) {
        for (int i = 0; i < 4; i++) { AS[i] = aPtr[i]; AD[i] = aPtr[4 + i]; }
    } else {
        for (int i = 0; i < 4; i++) { AS[i] = aPtr[2 * i]; AD[i] = aPtr[2 * i + 1]; }
    }

    float* hp;  cudaGetSymbolAddress((void**)&hp,  g_hp);
    float* xbuf;cudaGetSymbolAddress((void**)&xbuf,g_x);
    float* zbuf;cudaGetSymbolAddress((void**)&zbuf,g_z);
    float* zt;  cudaGetSymbolAddress((void**)&zt,  g_zt);

    float* out = (float*)d_out;
    const long long need = (long long)NN * NN + (long long)NN * FF;
    float* zmirror = ((long long)out_size >= need) ? out + (size_t)NN * NN : nullptr;

    // dtype detect + CSR build (once per launch, reused by all 4 layers)
    detect_ei_kernel<<<1, 256>>>(ei);
    csr_zero_kernel   <<<(NN + 255) / 256, 256>>>();
    csr_hist_kernel   <<<(ET + 255) / 256, 256>>>(ei);
    csr_scan_kernel   <<<1, 1024>>>();
    csr_scatter_kernel<<<(ET + 255) / 256, 256>>>(ei);

    run_layer(x,    NN, W[0], AS[0], AD[0], B[0], ei, hp, xbuf, 0, nullptr);
    run_layer(xbuf, FF, W[1], AS[1], AD[1], B[1], ei, hp, xbuf, 0, nullptr);
    run_layer(xbuf, FF, W[2], AS[2], AD[2], B[2], ei, hp, xbuf, 0, nullptr);
    run_layer(xbuf, FF, W[3], AS[3], AD[3], B[3], ei, hp, zbuf, 1, zmirror);

    // decode: adj = sigmoid(z @ z^T)
    transpose_z_kernel<<<(NN * FF + 255) / 256, 256>>>(zbuf, zt);
    {
        dim3 grid((NN + 127) / 128, (NN + 127) / 128);
        sgemm128<1><<<grid, 256>>>(NN, NN, FF, zbuf, zt, out);
    }
}

// round 7
// speedup vs baseline: 1.5459x; 1.0969x over previous
#include <cuda_runtime.h>
#include <math.h>
#include <stdint.h>

#define NN    10000
#define HH    4
#define FF    128
#define HF    (HH*FF)      // 512
#define EE    320000
#define ET    (EE+NN)      // 330000 edges incl self-loops
#define SLOPE 0.2f

// ---------------- scratch (device globals; no allocation allowed) ----------
__device__ float g_hp  [(size_t)NN*HF];   // projected features [N,H,F]
__device__ float g_x   [(size_t)NN*FF];   // inter-layer features [N,F]
__device__ float g_z   [(size_t)NN*FF];   // encoder output z [N,F]
__device__ float g_als [NN*HH];
__device__ float g_ald [NN*HH];
__device__ float g_eval[(size_t)ET*HH];   // per-edge exp values (CSR order)
__device__ int   g_is64;                  // edge_index dtype flag
// CSR by destination node
__device__ int   g_deg [NN];
__device__ int   g_off [NN+1];
__device__ int   g_cur [NN];
__device__ int   g_eid [ET];

// --------- edge-index dtype sniffer ----------------------------------------
__global__ void detect_ei_kernel(const int* __restrict__ ei32)
{
    __shared__ int any;
    if (threadIdx.x == 0) any = 0;
    __syncthreads();
    for (int i = threadIdx.x; i < 4096; i += blockDim.x)
        if (ei32[2 * i + 1] != 0) atomicOr(&any, 1);
    __syncthreads();
    if (threadIdx.x == 0) g_is64 = (any == 0);
}

__device__ __forceinline__ void edge_sd(const int* __restrict__ ei32, int e,
                                        int& s, int& d)
{
    if (e >= EE) { s = d = e - EE; return; }          // self-loop
    if (g_is64) { s = ei32[2 * e]; d = ei32[2 * (EE + e)]; }
    else        { s = ei32[e];     d = ei32[EE + e]; }
}

__device__ __forceinline__ bool valid_nd(int s, int d)
{
    return ((unsigned)s < NN) && ((unsigned)d < NN);
}

// ---------------- CSR construction ------------------------------------------
__global__ void csr_zero_kernel()
{
    const int n = blockIdx.x * blockDim.x + threadIdx.x;
    if (n < NN) g_deg[n] = 0;
}

__global__ void csr_hist_kernel(const int* __restrict__ ei)
{
    const int e = blockIdx.x * blockDim.x + threadIdx.x;
    if (e >= ET) return;
    int s, d; edge_sd(ei, e, s, d);
    if (valid_nd(s, d)) atomicAdd(&g_deg[d], 1);
}

__global__ void csr_scan_kernel()
{
    __shared__ int warp_sums[32];
    const int tid  = threadIdx.x;          // 1024 threads
    const int lane = tid & 31, wid = tid >> 5;
    const int base = tid * 10;

    int local[10];
    int sum = 0;
    #pragma unroll
    for (int k = 0; k < 10; k++) {
        const int n = base + k;
        const int v = (n < NN) ? g_deg[n] : 0;
        local[k] = sum;
        sum += v;
    }
    int x = sum;
    #pragma unroll
    for (int o = 1; o < 32; o <<= 1) {
        const int y = __shfl_up_sync(0xffffffffu, x, o);
        if (lane >= o) x += y;
    }
    if (lane == 31) warp_sums[wid] = x;
    __syncthreads();
    if (wid == 0) {
        int w = warp_sums[lane];
        #pragma unroll
        for (int o = 1; o < 32; o <<= 1) {
            const int y = __shfl_up_sync(0xffffffffu, w, o);
            if (lane >= o) w += y;
        }
        warp_sums[lane] = w;
    }
    __syncthreads();
    const int thread_excl = x - sum + (wid > 0 ? warp_sums[wid - 1] : 0);
    #pragma unroll
    for (int k = 0; k < 10; k++) {
        const int n = base + k;
        if (n < NN) {
            const int o = thread_excl + local[k];
            g_off[n] = o;
            g_cur[n] = o;
        }
    }
    if (tid == 1023) g_off[NN] = thread_excl + sum;
}

__global__ void csr_scatter_kernel(const int* __restrict__ ei)
{
    const int e = blockIdx.x * blockDim.x + threadIdx.x;
    if (e >= ET) return;
    int s, d; edge_sd(ei, e, s, d);
    if (!valid_nd(s, d)) return;
    const int pos = atomicAdd(&g_cur[d], 1);
    g_eid[pos] = e;
}

// ---------------- 3xTF32 tensor-core GEMM -----------------------------------
// C[M,N] = A[M,K] @ op(B).  TRANSB=false: B[K,N]; true: B[N,K] (C = A@B^T).
// ACT: 0=none, 1=sigmoid.  K % 16 == 0 required.
// Block 128x128, BK=16, 256 threads = 8 warps (2x4), warp tile 64x32.
// Operands split hi/lo at staging; 3 mma per product (hi*hi + hi*lo + lo*hi).

__device__ __forceinline__ uint32_t f2tf32(float f)
{
    uint32_t r;
    asm("cvt.rna.tf32.f32 %0, %1;" : "=r"(r) : "f"(f));
    return r;
}

__device__ __forceinline__ void mma_tf32(float4& d,
    uint32_t a0, uint32_t a1, uint32_t a2, uint32_t a3,
    uint32_t b0, uint32_t b1)
{
    asm volatile(
        "mma.sync.aligned.m16n8k8.row.col.f32.tf32.tf32.f32 "
        "{%0,%1,%2,%3},{%4,%5,%6,%7},{%8,%9},{%0,%1,%2,%3};"
        : "+f"(d.x), "+f"(d.y), "+f"(d.z), "+f"(d.w)
        : "r"(a0), "r"(a1), "r"(a2), "r"(a3), "r"(b0), "r"(b1));
}

template<int ACT, bool TRANSB>
__global__ __launch_bounds__(256)
void gemm_tf32(int M, int N, int K,
               const float* __restrict__ A,
               const float* __restrict__ B,
               float* __restrict__ C)
{
    __shared__ float Ah[16][132], Al[16][132];
    __shared__ float Bh[16][132], Bl[16][132];

    const int tid  = threadIdx.x;
    const int lane = tid & 31;
    const int warp = tid >> 5;
    const int warpM = (warp >> 2) * 64;      // 0 or 64
    const int warpN = (warp & 3) * 32;       // 0,32,64,96
    const int rowBase = blockIdx.y * 128;
    const int colBase = blockIdx.x * 128;

    // staging maps
    const int aRow = tid >> 2;               // 0..63 (and +64)
    const int aCol = (tid & 3) * 4;          // 0,4,8,12 (k offset)
    const int bRow = tid >> 5;               // 0..7 (and +8)   (K,N source)
    const int bCol = (tid & 31) * 4;         // 0..124
    // TRANSB source (N,K): nRow = n index, nCol = k offset
    const int nRow = tid >> 2;
    const int nCol = (tid & 3) * 4;

    float4 acc[4][4];
    #pragma unroll
    for (int i = 0; i < 4; i++)
        #pragma unroll
        for (int j = 0; j < 4; j++) acc[i][j] = make_float4(0.f, 0.f, 0.f, 0.f);

    for (int k0 = 0; k0 < K; k0 += 16) {
        // ---- stage A (hi/lo split) ----
        #pragma unroll
        for (int half = 0; half < 2; half++) {
            const int r = rowBase + aRow + half * 64;
            float4 av = make_float4(0.f, 0.f, 0.f, 0.f);
            if (r < M)
                av = *reinterpret_cast<const float4*>(&A[(size_t)r * K + k0 + aCol]);
            const float vv[4] = { av.x, av.y, av.z, av.w };
            #pragma unroll
            for (int i = 0; i < 4; i++) {
                const float f  = vv[i];
                const uint32_t hu = f2tf32(f);
                const float hf = __uint_as_float(hu);
                Ah[aCol + i][aRow + half * 64] = hf;
                Al[aCol + i][aRow + half * 64] = __uint_as_float(f2tf32(f - hf));
            }
        }
        // ---- stage B (hi/lo split) ----
        if (!TRANSB) {
            #pragma unroll
            for (int half = 0; half < 2; half++) {
                const int c = colBase + bCol;
                const int kr = k0 + bRow + half * 8;
                float4 bv = make_float4(0.f, 0.f, 0.f, 0.f);
                if (c < N)
                    bv = *reinterpret_cast<const float4*>(&B[(size_t)kr * N + c]);
                const float vv[4] = { bv.x, bv.y, bv.z, bv.w };
                #pragma unroll
                for (int i = 0; i < 4; i++) {
                    const float f  = vv[i];
                    const uint32_t hu = f2tf32(f);
                    const float hf = __uint_as_float(hu);
                    Bh[bRow + half * 8][bCol + i] = hf;
                    Bl[bRow + half * 8][bCol + i] = __uint_as_float(f2tf32(f - hf));
                }
            }
        } else {
            #pragma unroll
            for (int half = 0; half < 2; half++) {
                const int n = colBase + nRow + half * 64;
                float4 bv = make_float4(0.f, 0.f, 0.f, 0.f);
                if (n < N)
                    bv = *reinterpret_cast<const float4*>(&B[(size_t)n * K + k0 + nCol]);
                const float vv[4] = { bv.x, bv.y, bv.z, bv.w };
                #pragma unroll
                for (int i = 0; i < 4; i++) {
                    const float f  = vv[i];
                    const uint32_t hu = f2tf32(f);
                    const float hf = __uint_as_float(hu);
                    Bh[nCol + i][nRow + half * 64] = hf;
                    Bl[nCol + i][nRow + half * 64] = __uint_as_float(f2tf32(f - hf));
                }
            }
        }
        __syncthreads();

        // ---- two k8 steps ----
        #pragma unroll
        for (int s = 0; s < 2; s++) {
            const int c0 = s * 8 + (lane & 3);
            const int c1 = c0 + 4;
            const int r0 = warpM + (lane >> 2);
            const int bc = warpN + (lane >> 2);

            uint32_t ah[4][4], al[4][4];
            #pragma unroll
            for (int mi = 0; mi < 4; mi++) {
                const int rA = r0 + mi * 16;
                ah[mi][0] = __float_as_uint(Ah[c0][rA]);
                ah[mi][1] = __float_as_uint(Ah[c0][rA + 8]);
                ah[mi][2] = __float_as_uint(Ah[c1][rA]);
                ah[mi][3] = __float_as_uint(Ah[c1][rA + 8]);
                al[mi][0] = __float_as_uint(Al[c0][rA]);
                al[mi][1] = __float_as_uint(Al[c0][rA + 8]);
                al[mi][2] = __float_as_uint(Al[c1][rA]);
                al[mi][3] = __float_as_uint(Al[c1][rA + 8]);
            }
            uint32_t bh[4][2], bl[4][2];
            #pragma unroll
            for (int ni = 0; ni < 4; ni++) {
                const int cB = bc + ni * 8;
                bh[ni][0] = __float_as_uint(Bh[c0][cB]);
                bh[ni][1] = __float_as_uint(Bh[c1][cB]);
                bl[ni][0] = __float_as_uint(Bl[c0][cB]);
                bl[ni][1] = __float_as_uint(Bl[c1][cB]);
            }
            #pragma unroll
            for (int mi = 0; mi < 4; mi++)
                #pragma unroll
                for (int ni = 0; ni < 4; ni++) {
                    mma_tf32(acc[mi][ni], ah[mi][0], ah[mi][1], ah[mi][2], ah[mi][3],
                             bl[ni][0], bl[ni][1]);
                    mma_tf32(acc[mi][ni], al[mi][0], al[mi][1], al[mi][2], al[mi][3],
                             bh[ni][0], bh[ni][1]);
                    mma_tf32(acc[mi][ni], ah[mi][0], ah[mi][1], ah[mi][2], ah[mi][3],
                             bh[ni][0], bh[ni][1]);
                }
        }
        __syncthreads();
    }

    // ---- epilogue ----
    #pragma unroll
    for (int mi = 0; mi < 4; mi++) {
        const int r = rowBase + warpM + mi * 16 + (lane >> 2);
        #pragma unroll
        for (int ni = 0; ni < 4; ni++) {
            const int c = colBase + warpN + ni * 8 + 2 * (lane & 3);
            float v0 = acc[mi][ni].x, v1 = acc[mi][ni].y;
            float v2 = acc[mi][ni].z, v3 = acc[mi][ni].w;
            if (ACT == 1) {
                v0 = 1.f / (1.f + __expf(-v0));
                v1 = 1.f / (1.f + __expf(-v1));
                v2 = 1.f / (1.f + __expf(-v2));
                v3 = 1.f / (1.f + __expf(-v3));
            }
            if (r < M) {
                if (c < N)     C[(size_t)r * N + c]     = v0;
                if (c + 1 < N) C[(size_t)r * N + c + 1] = v1;
            }
            if (r + 8 < M) {
                if (c < N)     C[(size_t)(r + 8) * N + c]     = v2;
                if (c + 1 < N) C[(size_t)(r + 8) * N + c + 1] = v3;
            }
        }
    }
}

// --------- per-node attention logits ----------------------------------------
__global__ void attn_logits_kernel(const float* __restrict__ hp,
                                   const float* __restrict__ a_src,
                                   const float* __restrict__ a_dst)
{
    const int warp = (blockIdx.x * blockDim.x + threadIdx.x) >> 5;
    const int lane = threadIdx.x & 31;
    if (warp >= NN * HH) return;
    const int n = warp / HH, h = warp % HH;
    const float* hv = hp + (size_t)n * HF + h * FF;
    float s1 = 0.f, s2 = 0.f;
    #pragma unroll
    for (int j = 0; j < 4; j++) {
        const int f = lane + 32 * j;
        const float v = hv[f];
        s1 = fmaf(v, a_src[h * FF + f], s1);
        s2 = fmaf(v, a_dst[h * FF + f], s2);
    }
    #pragma unroll
    for (int o = 16; o; o >>= 1) {
        s1 += __shfl_xor_sync(0xffffffffu, s1, o);
        s2 += __shfl_xor_sync(0xffffffffu, s2, o);
    }
    if (lane == 0) { g_als[warp] = s1; g_ald[warp] = s2; }
}

// ---------------- fused per-dst-node softmax + aggregate --------------------
__global__ __launch_bounds__(128)
void fused_agg_kernel(const int* __restrict__ ei,
                      const float* __restrict__ b,
                      float* __restrict__ out, int act,
                      float* __restrict__ mirror)
{
    const int n   = blockIdx.x;
    const int tid = threadIdx.x;
    const int lane = tid & 31, wid = tid >> 5;
    const int off = g_off[n];
    const int deg = g_off[n + 1] - off;

    __shared__ float warp_red[4][4];
    __shared__ float smax[4], sinv[4];
    __shared__ float alpha_sm[128][4];
    __shared__ int   ssrc_sm[128];
    __shared__ float feat[HF];

    const float4 ald4 = *reinterpret_cast<const float4*>(&g_ald[n * 4]);

    float mx[4] = { -INFINITY, -INFINITY, -INFINITY, -INFINITY };
    for (int i = tid; i < deg; i += 128) {
        const int e = g_eid[off + i];
        int s, d; edge_sd(ei, e, s, d);
        const float4 as4 = *reinterpret_cast<const float4*>(&g_als[s * 4]);
        float v[4] = { as4.x + ald4.x, as4.y + ald4.y,
                       as4.z + ald4.z, as4.w + ald4.w };
        #pragma unroll
        for (int h = 0; h < 4; h++) {
            v[h] = v[h] > 0.f ? v[h] : SLOPE * v[h];
            mx[h] = fmaxf(mx[h], v[h]);
        }
        *reinterpret_cast<float4*>(&g_eval[(size_t)(off + i) * 4]) =
            make_float4(v[0], v[1], v[2], v[3]);
    }
    #pragma unroll
    for (int h = 0; h < 4; h++)
        #pragma unroll
        for (int o = 16; o; o >>= 1)
            mx[h] = fmaxf(mx[h], __shfl_xor_sync(0xffffffffu, mx[h], o));
    if (lane == 0)
        #pragma unroll
        for (int h = 0; h < 4; h++) warp_red[wid][h] = mx[h];
    __syncthreads();
    if (tid == 0) {
        #pragma unroll
        for (int h = 0; h < 4; h++)
            smax[h] = fmaxf(fmaxf(warp_red[0][h], warp_red[1][h]),
                            fmaxf(warp_red[2][h], warp_red[3][h]));
    }
    __syncthreads();

    float sm[4] = { 0.f, 0.f, 0.f, 0.f };
    const float m0 = smax[0], m1 = smax[1], m2 = smax[2], m3 = smax[3];
    for (int i = tid; i < deg; i += 128) {
        float4 v = *reinterpret_cast<const float4*>(&g_eval[(size_t)(off + i) * 4]);
        v.x = __expf(v.x - m0); v.y = __expf(v.y - m1);
        v.z = __expf(v.z - m2); v.w = __expf(v.w - m3);
        *reinterpret_cast<float4*>(&g_eval[(size_t)(off + i) * 4]) = v;
        sm[0] += v.x; sm[1] += v.y; sm[2] += v.z; sm[3] += v.w;
    }
    #pragma unroll
    for (int h = 0; h < 4; h++)
        #pragma unroll
        for (int o = 16; o; o >>= 1)
            sm[h] += __shfl_xor_sync(0xffffffffu, sm[h], o);
    if (lane == 0)
        #pragma unroll
        for (int h = 0; h < 4; h++) warp_red[wid][h] = sm[h];
    __syncthreads();
    if (tid == 0) {
        #pragma unroll
        for (int h = 0; h < 4; h++) {
            const float t = warp_red[0][h] + warp_red[1][h] +
                            warp_red[2][h] + warp_red[3][h];
            sinv[h] = (t > 0.f) ? 1.f / t : 0.f;
        }
    }
    __syncthreads();

    const int myh = tid >> 5;
    const float i0 = sinv[0], i1 = sinv[1], i2 = sinv[2], i3 = sinv[3];
    float4 acc = make_float4(0.f, 0.f, 0.f, 0.f);
    for (int base = 0; base < deg; base += 128) {
        const int cnt = min(128, deg - base);
        __syncthreads();
        if (tid < cnt) {
            const int e = g_eid[off + base + tid];
            int s, d; edge_sd(ei, e, s, d);
            ssrc_sm[tid] = s;
            const float4 v =
                *reinterpret_cast<const float4*>(&g_eval[(size_t)(off + base + tid) * 4]);
            alpha_sm[tid][0] = v.x * i0;
            alpha_sm[tid][1] = v.y * i1;
            alpha_sm[tid][2] = v.z * i2;
            alpha_sm[tid][3] = v.w * i3;
        }
        __syncthreads();
        for (int j = 0; j < cnt; j++) {
            const int s = ssrc_sm[j];
            const float a = alpha_sm[j][myh];
            const float4 hv = *reinterpret_cast<const float4*>(
                &g_hp[(size_t)s * HF + tid * 4]);
            acc.x = fmaf(a, hv.x, acc.x);
            acc.y = fmaf(a, hv.y, acc.y);
            acc.z = fmaf(a, hv.z, acc.z);
            acc.w = fmaf(a, hv.w, acc.w);
        }
    }
    *reinterpret_cast<float4*>(&feat[tid * 4]) = acc;
    __syncthreads();

    {
        const int f = tid;
        float v = (feat[f] + feat[FF + f] + feat[2 * FF + f] + feat[3 * FF + f])
                  * 0.25f + b[f];
        v = (act == 0) ? fmaxf(v, 0.f) : tanhf(v);
        out[(size_t)n * FF + f] = v;
        if (mirror) mirror[(size_t)n * FF + f] = v;
    }
}

// ---------------------------------------------------------------------------
static void run_layer(const float* x, int Din, const float* W,
                      const float* a_s, const float* a_d, const float* b,
                      const int* ei, float* hp, float* out, int act,
                      float* mirror)
{
    {
        dim3 grid((HF + 127) / 128, (NN + 127) / 128);
        gemm_tf32<0, false><<<grid, 256>>>(NN, HF, Din, x, W, hp);
    }
    attn_logits_kernel<<<(NN * HH * 32 + 255) / 256, 256>>>(hp, a_s, a_d);
    fused_agg_kernel<<<NN, 128>>>(ei, b, out, act, mirror);
}

extern "C" void kernel_launch(void* const* d_in, const int* in_sizes, int n_in,
                              void* d_out, int out_size)
{
    // ---- size-based input classification ----------------------------------
    const int SZ_X  = NN * NN;
    const int SZ_EI = 2 * EE;
    const int SZ_W0 = NN * HF;
    const int SZ_W  = FF * HF;
    const int SZ_A  = HH * FF;
    const int SZ_B  = FF;

    const float* x  = nullptr;
    const int*   ei = nullptr;
    const float* W [4] = {nullptr, nullptr, nullptr, nullptr};
    const float* AS[4] = {nullptr, nullptr, nullptr, nullptr};
    const float* AD[4] = {nullptr, nullptr, nullptr, nullptr};
    const float* B [4] = {nullptr, nullptr, nullptr, nullptr};

    int wIdx = 1, bIdx = 0;
    int aPos[8]; const float* aPtr[8]; int nA = 0;

    for (int i = 0; i < n_in; i++) {
        const int s = in_sizes[i];
        if      (s == SZ_X)  x = (const float*)d_in[i];
        else if (s == SZ_EI) ei = (const int*)d_in[i];
        else if (s == SZ_W0) W[0] = (const float*)d_in[i];
        else if (s == SZ_W)  { if (wIdx < 4) W[wIdx++] = (const float*)d_in[i]; }
        else if (s == SZ_A)  { if (nA < 8) { aPos[nA] = i; aPtr[nA] = (const float*)d_in[i]; nA++; } }
        else if (s == SZ_B)  { if (bIdx < 4) B[bIdx++] = (const float*)d_in[i]; }
    }

    bool contiguous8 = (nA == 8);
    for (int i = 1; i < nA; i++)
        if (aPos[i] != aPos[0] + i) { contiguous8 = false; break; }

    if (contiguous8) {
        for (int i = 0; i < 4; i++) { AS[i] = aPtr[i]; AD[i] = aPtr[4 + i]; }
    } else {
        for (int i = 0; i < 4; i++) { AS[i] = aPtr[2 * i]; AD[i] = aPtr[2 * i + 1]; }
    }

    float* hp;  cudaGetSymbolAddress((void**)&hp,  g_hp);
    float* xbuf;cudaGetSymbolAddress((void**)&xbuf,g_x);
    float* zbuf;cudaGetSymbolAddress((void**)&zbuf,g_z);

    float* out = (float*)d_out;
    const long long need = (long long)NN * NN + (long long)NN * FF;
    float* zmirror = ((long long)out_size >= need) ? out + (size_t)NN * NN : nullptr;

    // launch order arranged so the layer-0 GEMM is the 4th launch (ncu capture)
    detect_ei_kernel<<<1, 256>>>(ei);
    csr_zero_kernel <<<(NN + 255) / 256, 256>>>();
    csr_hist_kernel <<<(ET + 255) / 256, 256>>>(ei);
    {
        dim3 grid((HF + 127) / 128, (NN + 127) / 128);
        gemm_tf32<0, false><<<grid, 256>>>(NN, HF, NN, x, W[0], hp);   // 4th launch
    }
    csr_scan_kernel   <<<1, 1024>>>();
    csr_scatter_kernel<<<(ET + 255) / 256, 256>>>(ei);

    attn_logits_kernel<<<(NN * HH * 32 + 255) / 256, 256>>>(hp, AS[0], AD[0]);
    fused_agg_kernel<<<NN, 128>>>(ei, B[0], xbuf, 0, nullptr);

    run_layer(xbuf, FF, W[1], AS[1], AD[1], B[1], ei, hp, xbuf, 0, nullptr);
    run_layer(xbuf, FF, W[2], AS[2], AD[2], B[2], ei, hp, xbuf, 0, nullptr);
    run_layer(xbuf, FF, W[3], AS[3], AD[3], B[3], ei, hp, zbuf, 1, zmirror);

    // decode: adj = sigmoid(z @ z^T)  (TRANSB path, B staged from z[N,K])
    {
        dim3 grid((NN + 127) / 128, (NN + 127) / 128);
        gemm_tf32<1, true><<<grid, 256>>>(NN, NN, FF, zbuf, zbuf, out);
    }
}

// round 8
// speedup vs baseline: 2.4303x; 1.5720x over previous
#include <cuda_runtime.h>
#include <math.h>
#include <stdint.h>

#define NN    10000
#define HH    4
#define FF    128
#define HF    (HH*FF)      // 512
#define EE    320000
#define ET    (EE+NN)      // 330000 edges incl self-loops
#define SLOPE 0.2f

// ---------------- scratch (device globals; no allocation allowed) ----------
__device__ float g_hp  [(size_t)NN*HF];   // projected features [N,H,F]
__device__ float g_x   [(size_t)NN*FF];   // inter-layer features [N,F]
__device__ float g_z   [(size_t)NN*FF];   // encoder output z [N,F]
__device__ float g_als [NN*HH];
__device__ float g_ald [NN*HH];
__device__ float g_eval[(size_t)ET*HH];   // per-edge exp values (CSR order)
__device__ int   g_is64;                  // edge_index dtype flag
// CSR by destination node
__device__ int   g_deg [NN];
__device__ int   g_off [NN+1];
__device__ int   g_cur [NN];
__device__ int   g_eid [ET];

// --------- edge-index dtype sniffer ----------------------------------------
__global__ void detect_ei_kernel(const int* __restrict__ ei32)
{
    __shared__ int any;
    if (threadIdx.x == 0) any = 0;
    __syncthreads();
    for (int i = threadIdx.x; i < 4096; i += blockDim.x)
        if (ei32[2 * i + 1] != 0) atomicOr(&any, 1);
    __syncthreads();
    if (threadIdx.x == 0) g_is64 = (any == 0);
}

__device__ __forceinline__ void edge_sd(const int* __restrict__ ei32, int e,
                                        int& s, int& d)
{
    if (e >= EE) { s = d = e - EE; return; }          // self-loop
    if (g_is64) { s = ei32[2 * e]; d = ei32[2 * (EE + e)]; }
    else        { s = ei32[e];     d = ei32[EE + e]; }
}

__device__ __forceinline__ bool valid_nd(int s, int d)
{
    return ((unsigned)s < NN) && ((unsigned)d < NN);
}

// ---------------- CSR construction ------------------------------------------
__global__ void csr_zero_kernel()
{
    const int n = blockIdx.x * blockDim.x + threadIdx.x;
    if (n < NN) g_deg[n] = 0;
}

__global__ void csr_hist_kernel(const int* __restrict__ ei)
{
    const int e = blockIdx.x * blockDim.x + threadIdx.x;
    if (e >= ET) return;
    int s, d; edge_sd(ei, e, s, d);
    if (valid_nd(s, d)) atomicAdd(&g_deg[d], 1);
}

__global__ void csr_scan_kernel()
{
    __shared__ int warp_sums[32];
    const int tid  = threadIdx.x;          // 1024 threads
    const int lane = tid & 31, wid = tid >> 5;
    const int base = tid * 10;

    int local[10];
    int sum = 0;
    #pragma unroll
    for (int k = 0; k < 10; k++) {
        const int n = base + k;
        const int v = (n < NN) ? g_deg[n] : 0;
        local[k] = sum;
        sum += v;
    }
    int x = sum;
    #pragma unroll
    for (int o = 1; o < 32; o <<= 1) {
        const int y = __shfl_up_sync(0xffffffffu, x, o);
        if (lane >= o) x += y;
    }
    if (lane == 31) warp_sums[wid] = x;
    __syncthreads();
    if (wid == 0) {
        int w = warp_sums[lane];
        #pragma unroll
        for (int o = 1; o < 32; o <<= 1) {
            const int y = __shfl_up_sync(0xffffffffu, w, o);
            if (lane >= o) w += y;
        }
        warp_sums[lane] = w;
    }
    __syncthreads();
    const int thread_excl = x - sum + (wid > 0 ? warp_sums[wid - 1] : 0);
    #pragma unroll
    for (int k = 0; k < 10; k++) {
        const int n = base + k;
        if (n < NN) {
            const int o = thread_excl + local[k];
            g_off[n] = o;
            g_cur[n] = o;
        }
    }
    if (tid == 1023) g_off[NN] = thread_excl + sum;
}

__global__ void csr_scatter_kernel(const int* __restrict__ ei)
{
    const int e = blockIdx.x * blockDim.x + threadIdx.x;
    if (e >= ET) return;
    int s, d; edge_sd(ei, e, s, d);
    if (!valid_nd(s, d)) return;
    const int pos = atomicAdd(&g_cur[d], 1);
    g_eid[pos] = e;
}

// ---------------- 3xTF32 tensor-core GEMM, cp.async double-buffered ---------
// C[M,N] = A[M,K] @ op(B).  TRANSB=false: B[K,N]; true: B[N,K] (C = A@B^T).
// ACT: 0=none, 1=sigmoid.  K % 16 == 0 required.
// Block 128x128, BK=16, 256 threads = 8 warps (2x4), warp tile 64x32.
// Raw f32 staged via cp.async; hi/lo tf32 split at fragment load;
// 3 mma per logical product (hi*lo + lo*hi + hi*hi).

__device__ __forceinline__ uint32_t f2tf32(float f)
{
    uint32_t r;
    asm("cvt.rna.tf32.f32 %0, %1;" : "=r"(r) : "f"(f));
    return r;
}

__device__ __forceinline__ void mma_tf32(float4& d,
    uint32_t a0, uint32_t a1, uint32_t a2, uint32_t a3,
    uint32_t b0, uint32_t b1)
{
    asm volatile(
        "mma.sync.aligned.m16n8k8.row.col.f32.tf32.tf32.f32 "
        "{%0,%1,%2,%3},{%4,%5,%6,%7},{%8,%9},{%0,%1,%2,%3};"
        : "+f"(d.x), "+f"(d.y), "+f"(d.z), "+f"(d.w)
        : "r"(a0), "r"(a1), "r"(a2), "r"(a3), "r"(b0), "r"(b1));
}

__device__ __forceinline__ void cp16(uint32_t dst, const void* src, int sz)
{
    asm volatile("cp.async.ca.shared.global [%0], [%1], 16, %2;"
                 :: "r"(dst), "l"(src), "r"(sz));
}

// A (and B^T) smem layout: [row][20] (16 k + 4 pad); bank = (20r+k)%32, conflict-free.
// B (K,N)    smem layout: [k][136] (128 n + 8 pad); bank = (8k+n)%32, conflict-free.
#define PA 20
#define PB 136

template<int ACT, bool TRANSB>
__global__ __launch_bounds__(256, 2)
void gemm_tf32(int M, int N, int K,
               const float* __restrict__ A,
               const float* __restrict__ B,
               float* __restrict__ C)
{
    __shared__ float Asm[2][128 * PA];       // 2 x 10240 B
    __shared__ float Bsm[2][128 * PA];       // trans: [128][20]; notrans uses [16][136] (2176 floats)

    const int tid  = threadIdx.x;
    const int lane = tid & 31;
    const int warp = tid >> 5;
    const int warpM = (warp >> 2) * 64;      // 0 or 64
    const int warpN = (warp & 3) * 32;       // 0,32,64,96
    const int rowBase = blockIdx.y * 128;
    const int colBase = blockIdx.x * 128;

    float4 acc[4][4];
    #pragma unroll
    for (int i = 0; i < 4; i++)
        #pragma unroll
        for (int j = 0; j < 4; j++) acc[i][j] = make_float4(0.f, 0.f, 0.f, 0.f);

    const int T = K >> 4;

    auto issue_tile = [&](int t, int bufi) {
        const int k0 = t << 4;
        // A: 128 rows x 16 k = 512 16B-chunks; 2 per thread
        #pragma unroll
        for (int c = 0; c < 2; c++) {
            const int chunk = tid * 2 + c;
            const int row   = chunk >> 2;
            const int kc    = (chunk & 3) << 2;
            const float* src = A + (size_t)(rowBase + row) * K + k0 + kc;
            const uint32_t dst =
                (uint32_t)__cvta_generic_to_shared(&Asm[bufi][row * PA + kc]);
            cp16(dst, src, (rowBase + row < M) ? 16 : 0);
        }
        if (!TRANSB) {
            // B[K,N]: 16 k-rows x 128 n
            #pragma unroll
            for (int c = 0; c < 2; c++) {
                const int chunk = tid * 2 + c;
                const int kr = chunk >> 5;           // 0..15
                const int nc = (chunk & 31) << 2;    // 0..124
                const float* src = B + (size_t)(k0 + kr) * N + colBase + nc;
                const uint32_t dst =
                    (uint32_t)__cvta_generic_to_shared(&Bsm[bufi][kr * PB + nc]);
                cp16(dst, src, (colBase + nc < N) ? 16 : 0);
            }
        } else {
            // B[N,K]: 128 n-rows x 16 k
            #pragma unroll
            for (int c = 0; c < 2; c++) {
                const int chunk = tid * 2 + c;
                const int row = chunk >> 2;
                const int kc  = (chunk & 3) << 2;
                const float* src = B + (size_t)(colBase + row) * K + k0 + kc;
                const uint32_t dst =
                    (uint32_t)__cvta_generic_to_shared(&Bsm[bufi][row * PA + kc]);
                cp16(dst, src, (colBase + row < N) ? 16 : 0);
            }
        }
        asm volatile("cp.async.commit_group;");
    };

    issue_tile(0, 0);

    int bufi = 0;
    for (int t = 0; t < T; t++) {
        if (t + 1 < T) {
            issue_tile(t + 1, bufi ^ 1);
            asm volatile("cp.async.wait_group 1;");
        } else {
            asm volatile("cp.async.wait_group 0;");
        }
        __syncthreads();

        const float* __restrict__ Ab = Asm[bufi];
        const float* __restrict__ Bb = Bsm[bufi];

        #pragma unroll
        for (int s = 0; s < 2; s++) {
            const int c0 = (s << 3) + (lane & 3);
            const int c1 = c0 + 4;
            const int r0 = warpM + (lane >> 2);
            const int bc = warpN + (lane >> 2);

            uint32_t ah[4][4], al[4][4];
            #pragma unroll
            for (int mi = 0; mi < 4; mi++) {
                const int rA = r0 + mi * 16;
                const float f0 = Ab[rA * PA + c0];
                const float f1 = Ab[(rA + 8) * PA + c0];
                const float f2 = Ab[rA * PA + c1];
                const float f3 = Ab[(rA + 8) * PA + c1];
                ah[mi][0] = f2tf32(f0);
                ah[mi][1] = f2tf32(f1);
                ah[mi][2] = f2tf32(f2);
                ah[mi][3] = f2tf32(f3);
                al[mi][0] = f2tf32(f0 - __uint_as_float(ah[mi][0]));
                al[mi][1] = f2tf32(f1 - __uint_as_float(ah[mi][1]));
                al[mi][2] = f2tf32(f2 - __uint_as_float(ah[mi][2]));
                al[mi][3] = f2tf32(f3 - __uint_as_float(ah[mi][3]));
            }
            #pragma unroll
            for (int ni = 0; ni < 4; ni++) {
                const int cB = bc + ni * 8;
                const float g0 = TRANSB ? Bb[cB * PA + c0] : Bb[c0 * PB + cB];
                const float g1 = TRANSB ? Bb[cB * PA + c1] : Bb[c1 * PB + cB];
                const uint32_t bh0 = f2tf32(g0);
                const uint32_t bh1 = f2tf32(g1);
                const uint32_t bl0 = f2tf32(g0 - __uint_as_float(bh0));
                const uint32_t bl1 = f2tf32(g1 - __uint_as_float(bh1));
                #pragma unroll
                for (int mi = 0; mi < 4; mi++) {
                    mma_tf32(acc[mi][ni], ah[mi][0], ah[mi][1], ah[mi][2], ah[mi][3],
                             bl0, bl1);
                    mma_tf32(acc[mi][ni], al[mi][0], al[mi][1], al[mi][2], al[mi][3],
                             bh0, bh1);
                    mma_tf32(acc[mi][ni], ah[mi][0], ah[mi][1], ah[mi][2], ah[mi][3],
                             bh0, bh1);
                }
            }
        }
        __syncthreads();
        bufi ^= 1;
    }

    // ---- epilogue ----
    #pragma unroll
    for (int mi = 0; mi < 4; mi++) {
        const int r = rowBase + warpM + mi * 16 + (lane >> 2);
        #pragma unroll
        for (int ni = 0; ni < 4; ni++) {
            const int c = colBase + warpN + ni * 8 + 2 * (lane & 3);
            float v0 = acc[mi][ni].x, v1 = acc[mi][ni].y;
            float v2 = acc[mi][ni].z, v3 = acc[mi][ni].w;
            if (ACT == 1) {
                v0 = 1.f / (1.f + __expf(-v0));
                v1 = 1.f / (1.f + __expf(-v1));
                v2 = 1.f / (1.f + __expf(-v2));
                v3 = 1.f / (1.f + __expf(-v3));
            }
            if (r < M) {
                if (c < N)     C[(size_t)r * N + c]     = v0;
                if (c + 1 < N) C[(size_t)r * N + c + 1] = v1;
            }
            if (r + 8 < M) {
                if (c < N)     C[(size_t)(r + 8) * N + c]     = v2;
                if (c + 1 < N) C[(size_t)(r + 8) * N + c + 1] = v3;
            }
        }
    }
}

// --------- per-node attention logits ----------------------------------------
__global__ void attn_logits_kernel(const float* __restrict__ hp,
                                   const float* __restrict__ a_src,
                                   const float* __restrict__ a_dst)
{
    const int warp = (blockIdx.x * blockDim.x + threadIdx.x) >> 5;
    const int lane = threadIdx.x & 31;
    if (warp >= NN * HH) return;
    const int n = warp / HH, h = warp % HH;
    const float* hv = hp + (size_t)n * HF + h * FF;
    float s1 = 0.f, s2 = 0.f;
    #pragma unroll
    for (int j = 0; j < 4; j++) {
        const int f = lane + 32 * j;
        const float v = hv[f];
        s1 = fmaf(v, a_src[h * FF + f], s1);
        s2 = fmaf(v, a_dst[h * FF + f], s2);
    }
    #pragma unroll
    for (int o = 16; o; o >>= 1) {
        s1 += __shfl_xor_sync(0xffffffffu, s1, o);
        s2 += __shfl_xor_sync(0xffffffffu, s2, o);
    }
    if (lane == 0) { g_als[warp] = s1; g_ald[warp] = s2; }
}

// ---------------- fused per-dst-node softmax + aggregate --------------------
__global__ __launch_bounds__(128)
void fused_agg_kernel(const int* __restrict__ ei,
                      const float* __restrict__ b,
                      float* __restrict__ out, int act,
                      float* __restrict__ mirror)
{
    const int n   = blockIdx.x;
    const int tid = threadIdx.x;
    const int lane = tid & 31, wid = tid >> 5;
    const int off = g_off[n];
    const int deg = g_off[n + 1] - off;

    __shared__ float warp_red[4][4];
    __shared__ float smax[4], sinv[4];
    __shared__ float alpha_sm[128][4];
    __shared__ int   ssrc_sm[128];
    __shared__ float feat[HF];

    const float4 ald4 = *reinterpret_cast<const float4*>(&g_ald[n * 4]);

    float mx[4] = { -INFINITY, -INFINITY, -INFINITY, -INFINITY };
    for (int i = tid; i < deg; i += 128) {
        const int e = g_eid[off + i];
        int s, d; edge_sd(ei, e, s, d);
        const float4 as4 = *reinterpret_cast<const float4*>(&g_als[s * 4]);
        float v[4] = { as4.x + ald4.x, as4.y + ald4.y,
                       as4.z + ald4.z, as4.w + ald4.w };
        #pragma unroll
        for (int h = 0; h < 4; h++) {
            v[h] = v[h] > 0.f ? v[h] : SLOPE * v[h];
            mx[h] = fmaxf(mx[h], v[h]);
        }
        *reinterpret_cast<float4*>(&g_eval[(size_t)(off + i) * 4]) =
            make_float4(v[0], v[1], v[2], v[3]);
    }
    #pragma unroll
    for (int h = 0; h < 4; h++)
        #pragma unroll
        for (int o = 16; o; o >>= 1)
            mx[h] = fmaxf(mx[h], __shfl_xor_sync(0xffffffffu, mx[h], o));
    if (lane == 0)
        #pragma unroll
        for (int h = 0; h < 4; h++) warp_red[wid][h] = mx[h];
    __syncthreads();
    if (tid == 0) {
        #pragma unroll
        for (int h = 0; h < 4; h++)
            smax[h] = fmaxf(fmaxf(warp_red[0][h], warp_red[1][h]),
                            fmaxf(warp_red[2][h], warp_red[3][h]));
    }
    __syncthreads();

    float sm[4] = { 0.f, 0.f, 0.f, 0.f };
    const float m0 = smax[0], m1 = smax[1], m2 = smax[2], m3 = smax[3];
    for (int i = tid; i < deg; i += 128) {
        float4 v = *reinterpret_cast<const float4*>(&g_eval[(size_t)(off + i) * 4]);
        v.x = __expf(v.x - m0); v.y = __expf(v.y - m1);
        v.z = __expf(v.z - m2); v.w = __expf(v.w - m3);
        *reinterpret_cast<float4*>(&g_eval[(size_t)(off + i) * 4]) = v;
        sm[0] += v.x; sm[1] += v.y; sm[2] += v.z; sm[3] += v.w;
    }
    #pragma unroll
    for (int h = 0; h < 4; h++)
        #pragma unroll
        for (int o = 16; o; o >>= 1)
            sm[h] += __shfl_xor_sync(0xffffffffu, sm[h], o);
    if (lane == 0)
        #pragma unroll
        for (int h = 0; h < 4; h++) warp_red[wid][h] = sm[h];
    __syncthreads();
    if (tid == 0) {
        #pragma unroll
        for (int h = 0; h < 4; h++) {
            const float t = warp_red[0][h] + warp_red[1][h] +
                            warp_red[2][h] + warp_red[3][h];
            sinv[h] = (t > 0.f) ? 1.f / t : 0.f;
        }
    }
    __syncthreads();

    const int myh = tid >> 5;
    const float i0 = sinv[0], i1 = sinv[1], i2 = sinv[2], i3 = sinv[3];
    float4 acc = make_float4(0.f, 0.f, 0.f, 0.f);
    for (int base = 0; base < deg; base += 128) {
        const int cnt = min(128, deg - base);
        __syncthreads();
        if (tid < cnt) {
            const int e = g_eid[off + base + tid];
            int s, d; edge_sd(ei, e, s, d);
            ssrc_sm[tid] = s;
            const float4 v =
                *reinterpret_cast<const float4*>(&g_eval[(size_t)(off + base + tid) * 4]);
            alpha_sm[tid][0] = v.x * i0;
            alpha_sm[tid][1] = v.y * i1;
            alpha_sm[tid][2] = v.z * i2;
            alpha_sm[tid][3] = v.w * i3;
        }
        __syncthreads();
        for (int j = 0; j < cnt; j++) {
            const int s = ssrc_sm[j];
            const float a = alpha_sm[j][myh];
            const float4 hv = *reinterpret_cast<const float4*>(
                &g_hp[(size_t)s * HF + tid * 4]);
            acc.x = fmaf(a, hv.x, acc.x);
            acc.y = fmaf(a, hv.y, acc.y);
            acc.z = fmaf(a, hv.z, acc.z);
            acc.w = fmaf(a, hv.w, acc.w);
        }
    }
    *reinterpret_cast<float4*>(&feat[tid * 4]) = acc;
    __syncthreads();

    {
        const int f = tid;
        float v = (feat[f] + feat[FF + f] + feat[2 * FF + f] + feat[3 * FF + f])
                  * 0.25f + b[f];
        v = (act == 0) ? fmaxf(v, 0.f) : tanhf(v);
        out[(size_t)n * FF + f] = v;
        if (mirror) mirror[(size_t)n * FF + f] = v;
    }
}

// ---------------------------------------------------------------------------
static void run_layer(const float* x, int Din, const float* W,
                      const float* a_s, const float* a_d, const float* b,
                      const int* ei, float* hp, float* out, int act,
                      float* mirror)
{
    {
        dim3 grid((HF + 127) / 128, (NN + 127) / 128);
        gemm_tf32<0, false><<<grid, 256>>>(NN, HF, Din, x, W, hp);
    }
    attn_logits_kernel<<<(NN * HH * 32 + 255) / 256, 256>>>(hp, a_s, a_d);
    fused_agg_kernel<<<NN, 128>>>(ei, b, out, act, mirror);
}

extern "C" void kernel_launch(void* const* d_in, const int* in_sizes, int n_in,
                              void* d_out, int out_size)
{
    // ---- size-based input classification ----------------------------------
    const int SZ_X  = NN * NN;
    const int SZ_EI = 2 * EE;
    const int SZ_W0 = NN * HF;
    const int SZ_W  = FF * HF;
    const int SZ_A  = HH * FF;
    const int SZ_B  = FF;

    const float* x  = nullptr;
    const int*   ei = nullptr;
    const float* W [4] = {nullptr, nullptr, nullptr, nullptr};
    const float* AS[4] = {nullptr, nullptr, nullptr, nullptr};
    const float* AD[4] = {nullptr, nullptr, nullptr, nullptr};
    const float* B [4] = {nullptr, nullptr, nullptr, nullptr};

    int wIdx = 1, bIdx = 0;
    int aPos[8]; const float* aPtr[8]; int nA = 0;

    for (int i = 0; i < n_in; i++) {
        const int s = in_sizes[i];
        if      (s == SZ_X)  x = (const float*)d_in[i];
        else if (s == SZ_EI) ei = (const int*)d_in[i];
        else if (s == SZ_W0) W[0] = (const float*)d_in[i];
        else if (s == SZ_W)  { if (wIdx < 4) W[wIdx++] = (const float*)d_in[i]; }
        else if (s == SZ_A)  { if (nA < 8) { aPos[nA] = i; aPtr[nA] = (const float*)d_in[i]; nA++; } }
        else if (s == SZ_B)  { if (bIdx < 4) B[bIdx++] = (const float*)d_in[i]; }
    }

    bool contiguous8 = (nA == 8);
    for (int i = 1; i < nA; i++)
        if (aPos[i] != aPos[0] + i) { contiguous8 = false; break; }

    if (contiguous8) {
        for (int i = 0; i < 4; i++) { AS[i] = aPtr[i]; AD[i] = aPtr[4 + i]; }
    } else {
        for (int i = 0; i < 4; i++) { AS[i] = aPtr[2 * i]; AD[i] = aPtr[2 * i + 1]; }
    }

    float* hp;  cudaGetSymbolAddress((void**)&hp,  g_hp);
    float* xbuf;cudaGetSymbolAddress((void**)&xbuf,g_x);
    float* zbuf;cudaGetSymbolAddress((void**)&zbuf,g_z);

    float* out = (float*)d_out;
    const long long need = (long long)NN * NN + (long long)NN * FF;
    float* zmirror = ((long long)out_size >= need) ? out + (size_t)NN * NN : nullptr;

    // launch order arranged so the layer-0 GEMM is the 4th launch (ncu capture)
    detect_ei_kernel<<<1, 256>>>(ei);
    csr_zero_kernel <<<(NN + 255) / 256, 256>>>();
    csr_hist_kernel <<<(ET + 255) / 256, 256>>>(ei);
    {
        dim3 grid((HF + 127) / 128, (NN + 127) / 128);
        gemm_tf32<0, false><<<grid, 256>>>(NN, HF, NN, x, W[0], hp);   // 4th launch
    }
    csr_scan_kernel   <<<1, 1024>>>();
    csr_scatter_kernel<<<(ET + 255) / 256, 256>>>(ei);

    attn_logits_kernel<<<(NN * HH * 32 + 255) / 256, 256>>>(hp, AS[0], AD[0]);
    fused_agg_kernel<<<NN, 128>>>(ei, B[0], xbuf, 0, nullptr);

    run_layer(xbuf, FF, W[1], AS[1], AD[1], B[1], ei, hp, xbuf, 0, nullptr);
    run_layer(xbuf, FF, W[2], AS[2], AD[2], B[2], ei, hp, xbuf, 0, nullptr);
    run_layer(xbuf, FF, W[3], AS[3], AD[3], B[3], ei, hp, zbuf, 1, zmirror);

    // decode: adj = sigmoid(z @ z^T)  (TRANSB path, B staged from z[N,K])
    {
        dim3 grid((NN + 127) / 128, (NN + 127) / 128);
        gemm_tf32<1, true><<<grid, 256>>>(NN, NN, FF, zbuf, zbuf, out);
    }
}